// round 4
// baseline (speedup 1.0000x reference)
#include <cuda_runtime.h>
#include <cuda_bf16.h>

// TripletLoss: loss = mean_t relu( ||a_t - p_t + eps||_2 - ||a_t - n_t + eps||_2 + margin )
// embeddings [N, 128] f32, triplet index arrays [T] int32. Output: 1 float.
// Single fused kernel: gather + distance + hinge + two-level reduction +
// last-block finalize (graph-safe, allocation-free, deterministic).

#define MARGIN 0.5f
#define EPS 1e-6f
#define D 128
#define WARPS_PER_BLOCK 8
#define THREADS (WARPS_PER_BLOCK * 32)
#define ITERS 4                   // triplets per warp
#define TRIPLETS_PER_BLOCK (WARPS_PER_BLOCK * ITERS)
#define MAX_BLOCKS 65536

__device__ float g_partials[MAX_BLOCKS];
__device__ unsigned int g_ticket;   // zero at module load; last block resets to 0 each run

__global__ __launch_bounds__(THREADS) void triplet_kernel(
    const float* __restrict__ emb,
    const int* __restrict__ a_idx,
    const int* __restrict__ p_idx,
    const int* __restrict__ n_idx,
    int T,
    float* __restrict__ out)
{
    const int warp_in_block = threadIdx.x >> 5;
    const int lane = threadIdx.x & 31;
    const int warp_global = blockIdx.x * WARPS_PER_BLOCK + warp_in_block;
    const int base = warp_global * ITERS;

    // ---- load indices (uniform per warp, broadcast) ----
    int ai[ITERS], pi[ITERS], ni[ITERS];
    bool valid[ITERS];
    #pragma unroll
    for (int k = 0; k < ITERS; k++) {
        int t = base + k;
        valid[k] = (t < T);
        int tt = valid[k] ? t : 0;
        ai[k] = a_idx[tt];
        pi[k] = p_idx[tt];
        ni[k] = n_idx[tt];
    }

    // ---- front-batch all 12 row loads (one float4 per lane per row) ----
    float4 a4[ITERS], p4[ITERS], n4[ITERS];
    #pragma unroll
    for (int k = 0; k < ITERS; k++) {
        a4[k] = ((const float4*)(emb + (size_t)ai[k] * D))[lane];
        p4[k] = ((const float4*)(emb + (size_t)pi[k] * D))[lane];
        n4[k] = ((const float4*)(emb + (size_t)ni[k] * D))[lane];
    }

    // ---- per-triplet distance + hinge ----
    float acc = 0.0f;   // lane-0 accumulates hinge values
    #pragma unroll
    for (int k = 0; k < ITERS; k++) {
        float dp0 = a4[k].x - p4[k].x + EPS;
        float dp1 = a4[k].y - p4[k].y + EPS;
        float dp2 = a4[k].z - p4[k].z + EPS;
        float dp3 = a4[k].w - p4[k].w + EPS;
        float sp = dp0 * dp0 + dp1 * dp1 + dp2 * dp2 + dp3 * dp3;

        float dn0 = a4[k].x - n4[k].x + EPS;
        float dn1 = a4[k].y - n4[k].y + EPS;
        float dn2 = a4[k].z - n4[k].z + EPS;
        float dn3 = a4[k].w - n4[k].w + EPS;
        float sn = dn0 * dn0 + dn1 * dn1 + dn2 * dn2 + dn3 * dn3;

        #pragma unroll
        for (int off = 16; off > 0; off >>= 1) {
            sp += __shfl_xor_sync(0xFFFFFFFFu, sp, off);
            sn += __shfl_xor_sync(0xFFFFFFFFu, sn, off);
        }

        if (lane == 0 && valid[k]) {
            float v = sqrtf(sp) - sqrtf(sn) + MARGIN;
            acc += (v > 0.0f) ? v : 0.0f;
        }
    }

    // ---- block reduction of lane-0 partials ----
    __shared__ float warp_part[WARPS_PER_BLOCK];
    if (lane == 0) warp_part[warp_in_block] = acc;
    __syncthreads();

    if (threadIdx.x == 0) {
        float s = 0.0f;
        #pragma unroll
        for (int w = 0; w < WARPS_PER_BLOCK; w++) s += warp_part[w];
        g_partials[blockIdx.x] = s;
    }

    // ---- last-block finalize ----
    __shared__ bool is_last;
    if (threadIdx.x == 0) {
        __threadfence();
        unsigned int c = atomicAdd(&g_ticket, 1u);
        is_last = (c == gridDim.x - 1);
    }
    __syncthreads();

    if (is_last) {
        float s = 0.0f;
        for (int i = threadIdx.x; i < (int)gridDim.x; i += THREADS)
            s += g_partials[i];

        #pragma unroll
        for (int off = 16; off > 0; off >>= 1)
            s += __shfl_xor_sync(0xFFFFFFFFu, s, off);

        __shared__ float fin_part[WARPS_PER_BLOCK];
        if (lane == 0) fin_part[warp_in_block] = s;
        __syncthreads();

        if (threadIdx.x == 0) {
            float total = 0.0f;
            #pragma unroll
            for (int w = 0; w < WARPS_PER_BLOCK; w++) total += fin_part[w];
            out[0] = total / (float)T;
            g_ticket = 0;   // reset for next graph replay (deterministic)
        }
    }
}

extern "C" void kernel_launch(void* const* d_in, const int* in_sizes, int n_in,
                              void* d_out, int out_size) {
    const float* emb   = (const float*)d_in[0];
    // d_in[1] = labels (unused; triplets already mined)
    const int* a_idx   = (const int*)d_in[2];
    const int* p_idx   = (const int*)d_in[3];
    const int* n_idx   = (const int*)d_in[4];
    float* out         = (float*)d_out;
    const int T        = in_sizes[2];

    int blocks = (T + TRIPLETS_PER_BLOCK - 1) / TRIPLETS_PER_BLOCK;
    if (blocks > MAX_BLOCKS) blocks = MAX_BLOCKS;  // T=262144 -> 8192 blocks
    triplet_kernel<<<blocks, THREADS>>>(emb, a_idx, p_idx, n_idx, T, out);
}